// round 16
// baseline (speedup 1.0000x reference)
#include <cuda_runtime.h>
#include <math.h>
#include <stdint.h>

#define B_ 8
#define T_ 16
#define N_ 1024
#define CS 48
#define GS 32
#define HH 150
#define G3 450
#define ONUM 1024
#define MAXA 160
#define MAXM 80
#define NTA 768
#define NTB 512
#define FLATCAP 256

// ------------- device scratch (no cudaMalloc allowed) -------------
__device__ float    g_gi[B_*T_*MAXM*G3];    // GRU input gates at m1 rows
__device__ float    g_h23[B_*T_*MAXM*HH];   // attention hidden at m23 rows
__device__ float    g_om23[B_*T_*HH];       // gated max-pool over m23 rows
__device__ float    g_hm1[B_*T_*MAXM*HH];   // h_m1 rows
__device__ unsigned g_om1u[B_*T_*152];      // ENCODED max over m1 rows
__device__ int      g_c1[B_*T_];
__device__ int      g_nhit[B_*T_];          // non-chain hit count
__device__ int      g_ccnt[B_*T_];          // chain hit count
__device__ int      g_hmeta[B_*T_*MAXM];    // non-chain: r | srcpos<<8 | is23<<16
__device__ int      g_cmeta[B_*T_*MAXM];    // chain:     r | srcpos<<8
__device__ float    g_WhT[G3*152];          // Wh transposed [450][152]

__device__ __forceinline__ unsigned fenc(float f){
    unsigned u = __float_as_uint(f);
    return (u & 0x80000000u) ? ~u : (u | 0x80000000u);
}
__device__ __forceinline__ float fdec(unsigned u){
    return (u & 0x80000000u) ? __uint_as_float(u ^ 0x80000000u) : __uint_as_float(~u);
}

// pack predicate bits for 1024 elements (32 per lane), MLP-32 loads
template<int STRIDE>
__device__ __forceinline__ unsigned pack_bits(const float* __restrict__ p, int lane) {
    float v[32];
    #pragma unroll
    for (int i = 0; i < 32; i++) v[i] = __ldg(p + (size_t)(i*32 + lane)*STRIDE);
    unsigned b = 0;
    #pragma unroll
    for (int i = 0; i < 32; i++) b |= (v[i] > 0.f ? 1u : 0u) << i;
    return b;
}

// ---------------- Phase A smem float offsets ----------------
#define AW_G 0
#define AW_Q 1536
#define AW_K 2560
#define AW_V 3584
#define AB_G 8384
#define AB_Q 8416
#define AB_K 8448
#define AB_V 8480
#define A_OM 8640     // 160 encoded max, om23
#define A_EC 8800     // 320x48
#define A_EP 24160    // 320x48
#define A_IN 39520    // 160x48
#define A_NP 47200    // 80x48 + pad
// overlays
#define A_CO 8800
#define A_QR 13920
#define A_Qb 24160
#define A_Kb 26720
#define A_Pb 29280
#define A_Vb 39520
#define A_OM1 51520   // 152 encoded max, om1 nonhit
#define A_BH  51672   // 456 (bh)
#define A_TOTF 52128  // -> byte 208512
#define A_SMEM 217056

__global__ void __launch_bounds__(NTA, 1) phaseA(
    const float* __restrict__ code_x, const float* __restrict__ divided,
    const float* __restrict__ neighbors, const float* __restrict__ adj,
    const float* __restrict__ c_emb, const float* __restrict__ n_emb,
    const float* __restrict__ u_emb,
    const float* __restrict__ Wg, const float* __restrict__ bg,
    const float* __restrict__ Wi, const float* __restrict__ bi,
    const float* __restrict__ Wq, const float* __restrict__ bq,
    const float* __restrict__ Wk, const float* __restrict__ bk,
    const float* __restrict__ Wv, const float* __restrict__ bv,
    const float* __restrict__ Wh, const float* __restrict__ bh)
{
    extern __shared__ float sm[];
    short* sh      = (short*)((char*)sm + A_TOTF*4);
    short* rowmap  = sh;              // 1024
    short* idxA    = sh + 1024;       // 160
    short* idxNb   = idxA + MAXA;
    short* idxAp   = idxNb + MAXA;
    short* idxNbp  = idxAp + MAXA;
    short* m1l     = idxNbp + MAXA;   // 80
    short* m23l    = m1l + MAXM;      // 80
    short* aiof1   = m23l + MAXM;     // 80
    short* lstC    = aiof1 + MAXM;    // 320
    short* lstP    = lstC + 2*MAXA;   // 320
    short* prevmap = lstP + 2*MAXA;   // 1024
    unsigned char* flags   = (unsigned char*)sm + 215648; // 80
    unsigned char* prevhit = (unsigned char*)sm + 215808; // 1024
    int* cnts      = (int*)((char*)sm + 216832);          // 8
    short* nhl     = (short*)((char*)sm + 216864);        // 80

    const int bt = blockIdx.x;
    const int t = bt & 15;
    const int tid = threadIdx.x, lane = tid & 31, wid = tid >> 5;
    const unsigned lt = (1u << lane) - 1u;

    // ===== region 0: init (float4 weight loads) =====
    for (int i = bt*NTA + tid; i < G3*152; i += 128*NTA) {
        int j = i / 152, k = i - j*152;
        g_WhT[i] = (k < HH) ? Wh[k*G3 + j] : 0.f;
    }
    for (int i = tid; i < (CS*GS)/4; i += NTA)
        ((float4*)(sm + AW_G))[i] = __ldg((const float4*)Wg + i);
    for (int i = tid; i < (GS*GS)/4; i += NTA) {
        ((float4*)(sm + AW_Q))[i] = __ldg((const float4*)Wq + i);
        ((float4*)(sm + AW_K))[i] = __ldg((const float4*)Wk + i);
    }
    for (int i = tid; i < (GS*HH)/4; i += NTA)
        ((float4*)(sm + AW_V))[i] = __ldg((const float4*)Wv + i);
    if (tid < GS) { sm[AB_G + tid] = bg[tid]; sm[AB_Q + tid] = bq[tid]; sm[AB_K + tid] = bk[tid]; }
    for (int i = tid; i < HH; i += NTA) sm[AB_V + i] = bv[i];
    for (int i = tid; i < G3; i += NTA) sm[A_BH + i] = bh[i];
    {
        unsigned negenc = fenc(-1e30f);
        for (int i = tid; i < 160; i += NTA) ((unsigned*)(sm + A_OM))[i] = negenc;
        for (int i = tid; i < 152; i += NTA) ((unsigned*)(sm + A_OM1))[i] = negenc;
    }
    for (int i = tid; i < N_; i += NTA) { prevmap[i] = -1; prevhit[i] = 0; }
    __syncthreads();

    // ===== region 1: parallel list building, one warp per list =====
    const int base0 = bt * N_;
    if (wid == 0) {            // active cur + rowmap
        unsigned bits = pack_bits<1>(code_x + base0, lane);
        int cnt = 0;
        #pragma unroll
        for (int i = 0; i < 32; i++) {
            unsigned mk = __ballot_sync(0xffffffffu, (bits >> i) & 1u);
            if ((bits >> i) & 1u) {
                int p = cnt + __popc(mk & lt);
                if (p < MAXA) { idxA[p] = (short)(i*32 + lane); rowmap[i*32 + lane] = (short)p; }
            }
            cnt += __popc(mk);
        }
        if (lane == 0) cnts[0] = min(cnt, MAXA);
    } else if (wid == 1) {     // neighbors cur
        unsigned bits = pack_bits<1>(neighbors + base0, lane);
        int cnt = 0;
        #pragma unroll
        for (int i = 0; i < 32; i++) {
            unsigned mk = __ballot_sync(0xffffffffu, (bits >> i) & 1u);
            if ((bits >> i) & 1u) {
                int p = cnt + __popc(mk & lt);
                if (p < MAXA) idxNb[p] = (short)(i*32 + lane);
            }
            cnt += __popc(mk);
        }
        if (lane == 0) cnts[1] = min(cnt, MAXA);
    } else if (wid == 2) {     // m1
        unsigned bits = pack_bits<3>(divided + (size_t)base0*3 + 0, lane);
        int cnt = 0;
        #pragma unroll
        for (int i = 0; i < 32; i++) {
            unsigned mk = __ballot_sync(0xffffffffu, (bits >> i) & 1u);
            if ((bits >> i) & 1u) {
                int p = cnt + __popc(mk & lt);
                if (p < MAXM) m1l[p] = (short)(i*32 + lane);
            }
            cnt += __popc(mk);
        }
        if (lane == 0) cnts[4] = min(cnt, MAXM);
    } else if (wid == 3) {     // m23 + flags
        unsigned b2 = pack_bits<3>(divided + (size_t)base0*3 + 1, lane);
        unsigned b3 = pack_bits<3>(divided + (size_t)base0*3 + 2, lane);
        unsigned be = b2 | b3;
        int cnt = 0;
        #pragma unroll
        for (int i = 0; i < 32; i++) {
            unsigned mk = __ballot_sync(0xffffffffu, (be >> i) & 1u);
            if ((be >> i) & 1u) {
                int p = cnt + __popc(mk & lt);
                if (p < MAXM) { m23l[p] = (short)(i*32 + lane); flags[p] = (b2 >> i) & 1u; }
            }
            cnt += __popc(mk);
        }
        if (lane == 0) cnts[5] = min(cnt, MAXM);
    } else if (wid == 4) {     // active prev
        if (t > 0) {
            unsigned bits = pack_bits<1>(code_x + base0 - N_, lane);
            int cnt = 0;
            #pragma unroll
            for (int i = 0; i < 32; i++) {
                unsigned mk = __ballot_sync(0xffffffffu, (bits >> i) & 1u);
                if ((bits >> i) & 1u) {
                    int p = cnt + __popc(mk & lt);
                    if (p < MAXA) idxAp[p] = (short)(i*32 + lane);
                }
                cnt += __popc(mk);
            }
            if (lane == 0) cnts[2] = min(cnt, MAXA);
        } else if (lane == 0) cnts[2] = 0;
    } else if (wid == 5) {     // neighbors prev
        if (t > 0) {
            unsigned bits = pack_bits<1>(neighbors + base0 - N_, lane);
            int cnt = 0;
            #pragma unroll
            for (int i = 0; i < 32; i++) {
                unsigned mk = __ballot_sync(0xffffffffu, (bits >> i) & 1u);
                if ((bits >> i) & 1u) {
                    int p = cnt + __popc(mk & lt);
                    if (p < MAXA) idxNbp[p] = (short)(i*32 + lane);
                }
                cnt += __popc(mk);
            }
            if (lane == 0) cnts[3] = min(cnt, MAXA);
        } else if (lane == 0) cnts[3] = 0;
    } else if (wid == 6 && t > 0) {  // prevmap: prev m1 positions
        unsigned bits = pack_bits<3>(divided + (size_t)(base0 - N_)*3 + 0, lane);
        int cnt = 0;
        #pragma unroll
        for (int i = 0; i < 32; i++) {
            unsigned mk = __ballot_sync(0xffffffffu, (bits >> i) & 1u);
            if ((bits >> i) & 1u) {
                int p = cnt + __popc(mk & lt);
                if (p < MAXM) prevmap[i*32 + lane] = (short)p;
            }
            cnt += __popc(mk);
        }
    } else if (wid == 7 && t > 0) {  // prevmap: prev m23 positions (valid t>=2)
        unsigned b2 = pack_bits<3>(divided + (size_t)(base0 - N_)*3 + 1, lane);
        unsigned b3 = pack_bits<3>(divided + (size_t)(base0 - N_)*3 + 2, lane);
        unsigned be = b2 | b3;
        int cnt = 0;
        #pragma unroll
        for (int i = 0; i < 32; i++) {
            unsigned mk = __ballot_sync(0xffffffffu, (be >> i) & 1u);
            if ((be >> i) & 1u) {
                int p = cnt + __popc(mk & lt);
                if (p < MAXM && t >= 2) prevmap[i*32 + lane] = (short)(p | 0x4000);
            }
            cnt += __popc(mk);
        }
    } else if (wid == 8 && t >= 2) { // prevhit (was node a hit at t-1?)
        const float* dp = divided + (size_t)(base0 - 2*N_)*3;
        for (int i0 = 0; i0 < 32; i0 += 8) {
            float a[8], b2[8], c[8];
            #pragma unroll
            for (int u = 0; u < 8; u++) {
                int n = (i0 + u)*32 + lane;
                a[u]  = __ldg(dp + n*3 + 0);
                b2[u] = __ldg(dp + n*3 + 1);
                c[u]  = __ldg(dp + n*3 + 2);
            }
            #pragma unroll
            for (int u = 0; u < 8; u++) {
                int n = (i0 + u)*32 + lane;
                prevhit[n] = (a[u] > 0.f) || (((b2[u] > 0.f) || (c[u] > 0.f)) && t >= 3);
            }
        }
    }
    __syncthreads();

    const int cA = cnts[0], cNb = cnts[1], cAp = cnts[2], cNbp = cnts[3];
    const int c1 = cnts[4], c23 = cnts[5];
    const int totC = cA + cNb, totP = cAp + cNbp;

    // ===== region 2: hit classification + staging =====
    if (wid == 0) {
        int nnc = 0, ncc = 0, nnh = 0;
        for (int base = 0; base < c1; base += 32) {
            int r = base + lane;
            int n = (r < c1) ? m1l[r] : 0;
            short pm = (r < c1) ? prevmap[n] : (short)-1;
            bool inb = r < c1;
            bool hit = inb && pm >= 0;
            bool is23 = hit && (pm & 0x4000);
            bool chain = hit && !is23 && prevhit[n];
            bool nonch = hit && !chain;
            bool nonhit = inb && !hit;
            unsigned mk1 = __ballot_sync(0xffffffffu, nonch);
            unsigned mk2 = __ballot_sync(0xffffffffu, chain);
            unsigned mk3 = __ballot_sync(0xffffffffu, nonhit);
            if (inb) {
                int srcpos = pm & 0x3FFF;
                if (nonch) {
                    int p = nnc + __popc(mk1 & lt);
                    g_hmeta[bt*MAXM + p] = r | (srcpos << 8) | ((is23 ? 1 : 0) << 16);
                }
                if (chain) {
                    int p = ncc + __popc(mk2 & lt);
                    g_cmeta[bt*MAXM + p] = r | (srcpos << 8);
                }
                if (nonhit) {
                    int p = nnh + __popc(mk3 & lt);
                    nhl[p] = (short)r;
                }
            }
            nnc += __popc(mk1); ncc += __popc(mk2); nnh += __popc(mk3);
        }
        if (lane == 0) { g_nhit[bt] = nnc; g_ccnt[bt] = ncc; g_c1[bt] = c1; cnts[6] = nnh; }
    }
    if (t > 0)
        for (int i = tid; i < c23; i += NTA)
            if ((flags[i] & 1) && neighbors[(bt - 1)*N_ + m23l[i]] > 0.f) flags[i] |= 2;
    {
        int c1p = (c1 + 7) & ~7;
        for (int i = tid; i < c1p; i += NTA) aiof1[i] = (i < c1) ? rowmap[m1l[i]] : (short)0;
    }
    for (int i = tid; i < totC; i += NTA) lstC[i] = (i < cA) ? idxA[i] : idxNb[i - cA];
    if (t > 0)
        for (int i = tid; i < totP; i += NTA) lstP[i] = (i < cAp) ? idxAp[i] : idxNbp[i - cAp];
    // embedding staging, 4-way manual unroll
    {
        int ntask = totC*12;
        for (int task = tid; task < ntask; task += 4*NTA) {
            float4 v[4]; int tt[4];
            #pragma unroll
            for (int u = 0; u < 4; u++) {
                int tk = task + u*NTA;
                if (tk < ntask) {
                    int j = tk / 12, c4 = tk - j*12;
                    int n = (j < cA) ? idxA[j] : idxNb[j - cA];
                    const float* basep = (j < cA) ? c_emb : n_emb;
                    v[u] = __ldg((const float4*)(basep + n*CS) + c4);
                    tt[u] = tk;
                } else tt[u] = -1;
            }
            #pragma unroll
            for (int u = 0; u < 4; u++)
                if (tt[u] >= 0) ((float4*)(sm + A_EC))[tt[u]] = v[u];
        }
    }
    if (t > 0) {
        int ntask = totP*12;
        for (int task = tid; task < ntask; task += 4*NTA) {
            float4 v[4]; int tt[4];
            #pragma unroll
            for (int u = 0; u < 4; u++) {
                int tk = task + u*NTA;
                if (tk < ntask) {
                    int j = tk / 12, c4 = tk - j*12;
                    int n = (j < cAp) ? idxAp[j] : idxNbp[j - cAp];
                    const float* basep = (j < cAp) ? c_emb : n_emb;
                    v[u] = __ldg((const float4*)(basep + n*CS) + c4);
                    tt[u] = tk;
                } else tt[u] = -1;
            }
            #pragma unroll
            for (int u = 0; u < 4; u++)
                if (tt[u] >= 0) ((float4*)(sm + A_EP))[tt[u]] = v[u];
        }
    }
    __syncthreads();

    // ---- S1: aggregation input at active rows (batch-16 prefetch) ----
    for (int task = tid; task < cA*4; task += NTA) {
        int ai = task >> 2, ch = (task & 3) * 12;
        const float* arow = adj + (size_t)idxA[ai] * N_;
        float acc[12];
        const float* e0 = sm + A_EC + ai*CS + ch;
        #pragma unroll
        for (int c = 0; c < 12; c++) acc[c] = e0[c];
        for (int j0 = 0; j0 < totC; j0 += 16) {
            float av[16];
            #pragma unroll
            for (int u = 0; u < 16; u++) {
                int j = j0 + u;
                av[u] = (j < totC) ? __ldg(arow + lstC[j]) : 0.f;
            }
            #pragma unroll
            for (int u = 0; u < 16; u++) {
                if (av[u] != 0.f) {
                    const float* er = sm + A_EC + (j0 + u)*CS + ch;
                    #pragma unroll
                    for (int c = 0; c < 12; c++) acc[c] += av[u] * er[c];
                }
            }
        }
        float* o = sm + A_IN + ai*CS + ch;
        #pragma unroll
        for (int c = 0; c < 12; c++) o[c] = acc[c];
    }
    // ---- S1b: no_{t-1} input at m2 rows ----
    if (t > 0)
        for (int task = tid; task < c23*4; task += NTA) {
            int mi = task >> 2, ch = (task & 3) * 12;
            float acc[12];
            #pragma unroll
            for (int c = 0; c < 12; c++) acc[c] = 0.f;
            if (flags[mi] & 2) {
                int m = m23l[mi];
                const float* arow = adj + (size_t)m * N_;
                const float* nr = n_emb + m*CS + ch;
                #pragma unroll
                for (int c = 0; c < 12; c++) acc[c] = nr[c];
                for (int j0 = 0; j0 < totP; j0 += 16) {
                    float av[16];
                    #pragma unroll
                    for (int u = 0; u < 16; u++) {
                        int j = j0 + u;
                        av[u] = (j < totP) ? __ldg(arow + lstP[j]) : 0.f;
                    }
                    #pragma unroll
                    for (int u = 0; u < 16; u++) {
                        if (av[u] != 0.f) {
                            const float* er = sm + A_EP + (j0 + u)*CS + ch;
                            #pragma unroll
                            for (int c = 0; c < 12; c++) acc[c] += av[u] * er[c];
                        }
                    }
                }
            }
            float* o = sm + A_NP + mi*CS + ch;
            #pragma unroll
            for (int c = 0; c < 12; c++) o[c] = acc[c];
        }
    __syncthreads();

    // ---- S2: co = lrelu(in48 @ Wg + bg); qrows ----
    for (int task = tid; task < cA*GS; task += NTA) {
        int ai = task >> 5, g = task & 31;
        float acc = sm[AB_G + g];
        const float* in = sm + A_IN + ai*CS;
        #pragma unroll 8
        for (int c = 0; c < CS; c++) acc += in[c] * sm[AW_G + c*GS + g];
        sm[A_CO + task] = acc > 0.f ? acc : 0.01f * acc;
    }
    if (t > 0)
        for (int task = tid; task < c23*GS; task += NTA) {
            int mi = task >> 5, g = task & 31;
            float v;
            if (flags[mi] & 1) {
                float acc = sm[AB_G + g];
                const float* in = sm + A_NP + mi*CS;
                #pragma unroll 8
                for (int c = 0; c < CS; c++) acc += in[c] * sm[AW_G + c*GS + g];
                v = acc > 0.f ? acc : 0.01f * acc;
            } else {
                v = u_emb[m23l[mi]*GS + g];
            }
            sm[A_QR + task] = v;
        }
    __syncthreads();

    // ---- S3: gi at m1 rows (Wi prefetch-16); q/k/v (t>0) ----
    if (c1 > 0) {
        int ng = (c1 + 7) >> 3;
        for (int task = tid; task < G3*ng; task += NTA) {
            int j = task % G3, grp = task / G3, r0 = grp * 8;
            float acc[8];
            int ai[8];
            #pragma unroll
            for (int g = 0; g < 8; g++) { acc[g] = 0.f; ai[g] = aiof1[r0 + g]; }
            #pragma unroll 1
            for (int c0 = 0; c0 < GS; c0 += 16) {
                float w[16];
                #pragma unroll
                for (int u = 0; u < 16; u++) w[u] = __ldg(Wi + (c0 + u)*G3 + j);
                #pragma unroll
                for (int u = 0; u < 16; u++) {
                    #pragma unroll
                    for (int g = 0; g < 8; g++)
                        acc[g] += sm[A_CO + ai[g]*GS + c0 + u] * w[u];
                }
            }
            float bij = __ldg(bi + j);
            int nr = min(8, c1 - r0);
            #pragma unroll
            for (int g = 0; g < 8; g++)
                if (g < nr) g_gi[((size_t)bt*MAXM + r0 + g)*G3 + j] = acc[g] + bij;
        }
    }
    if (t > 0 && c23 > 0) {
        for (int task = tid; task < c23*GS; task += NTA) {
            int i = task >> 5, a = task & 31;
            const float* qr = sm + A_QR + i*GS;
            int ai = rowmap[m23l[i]];
            const float* co = sm + A_CO + ai*GS;
            float accq = sm[AB_Q + a], acck = sm[AB_K + a];
            #pragma unroll
            for (int g = 0; g < GS; g++) {
                accq += qr[g] * sm[AW_Q + g*GS + a];
                acck += co[g] * sm[AW_K + g*GS + a];
            }
            sm[A_Qb + task] = accq;
            sm[A_Kb + task] = acck;
        }
        for (int task = tid; task < c23*HH; task += NTA) {
            int i = task / HH, h = task - i*HH;
            const float* qr = sm + A_QR + i*GS;
            float acc = sm[AB_V + h];
            #pragma unroll
            for (int g = 0; g < GS; g++) acc += qr[g] * sm[AW_V + g*HH + h];
            sm[A_Vb + i*HH + h] = acc;
        }
    }
    __syncthreads();

    // ---- S4: scores + softmax (warp per query) ----
    if (t > 0 && c23 > 0) {
        const float scale = 0.17677669529663687f;
        for (int i = wid; i < c23; i += NTA/32) {
            const float* qi = sm + A_Qb + i*GS;
            float mx = -1e30f;
            for (int j = lane; j < c23; j += 32) {
                const float* kj = sm + A_Kb + j*GS;
                float s = 0.f;
                #pragma unroll
                for (int g = 0; g < GS; g++) s += qi[g] * kj[g];
                s *= scale;
                sm[A_Pb + i*MAXM + j] = s;
                mx = fmaxf(mx, s);
            }
            for (int o = 16; o; o >>= 1) mx = fmaxf(mx, __shfl_xor_sync(0xffffffffu, mx, o));
            float sum = 0.f;
            for (int j = lane; j < c23; j += 32) {
                float e = __expf(sm[A_Pb + i*MAXM + j] - mx);
                sm[A_Pb + i*MAXM + j] = e; sum += e;
            }
            for (int o = 16; o; o >>= 1) sum += __shfl_xor_sync(0xffffffffu, sum, o);
            float inv = 1.f / sum;
            for (int j = lane; j < c23; j += 32) sm[A_Pb + i*MAXM + j] *= inv;
        }
    }
    __syncthreads();

    // ---- S5: h_m23 + om23 (4 independent accumulator chains) ----
    if (t > 0 && c23 > 0) {
        unsigned* OM = (unsigned*)(sm + A_OM);
        for (int task = tid; task < c23*HH; task += NTA) {
            int i = task / HH, h = task - i*HH;
            const float* pr = sm + A_Pb + i*MAXM;
            const float* vb = sm + A_Vb + h;
            float a0 = 0.f, a1 = 0.f, a2 = 0.f, a3 = 0.f;
            int j = 0;
            for (; j + 3 < c23; j += 4) {
                a0 += pr[j]     * vb[j*HH];
                a1 += pr[j + 1] * vb[(j + 1)*HH];
                a2 += pr[j + 2] * vb[(j + 2)*HH];
                a3 += pr[j + 3] * vb[(j + 3)*HH];
            }
            float acc = (a0 + a1) + (a2 + a3);
            for (; j < c23; j++) acc += pr[j] * vb[j*HH];
            float hv = tanhf(acc);
            g_h23[((size_t)bt*MAXM + i)*HH + h] = hv;
            atomicMax(OM + h, fenc(hv));
        }
    }
    // ---- S6: non-hit GRU rows via compact list ----
    {
        const int nnh = cnts[6];
        unsigned* OM1 = (unsigned*)(sm + A_OM1);
        const int ntask = nnh*HH;
        for (int task = tid; task < ntask; task += NTA) {
            int r = nhl[task / HH], h = task % HH;
            const float* g1 = g_gi + ((size_t)bt*MAXM + r)*G3;
            float gr = __ldg(g1 + h), gz = __ldg(g1 + 150 + h), gn = __ldg(g1 + 300 + h);
            float rr = 1.f / (1.f + __expf(-(gr + sm[A_BH + h])));
            float zz = 1.f / (1.f + __expf(-(gz + sm[A_BH + 150 + h])));
            float nn = tanhf(gn + rr * sm[A_BH + 300 + h]);
            float hv = (1.f - zz) * nn;
            g_hm1[((size_t)bt*MAXM + r)*HH + h] = hv;
            atomicMax(OM1 + h, fenc(hv));
        }
    }
    __syncthreads();
    for (int h = tid; h < HH; h += NTA) {
        g_om1u[bt*152 + h] = ((unsigned*)(sm + A_OM1))[h];
        g_om23[bt*HH + h] = (t > 0 && c23 > 0) ? fdec(((unsigned*)(sm + A_OM))[h]) : 0.f;
    }
}

// ---------------- Phase B: hits + chains + attention + classifier ----------------
__global__ void __launch_bounds__(NTB, 1) phaseB(
    const int* __restrict__ lens,
    const float* __restrict__ bh,
    const float* __restrict__ Wd, const float* __restrict__ bd,
    const float* __restrict__ context,
    const float* __restrict__ Wc, const float* __restrict__ bc,
    float* __restrict__ out)
{
    __shared__ float OUTs[T_*HH];
    __shared__ float SWd[HH*GS];
    __shared__ float HP[4*152];
    __shared__ float GH[4*G3];
    __shared__ float BH[G3];
    __shared__ unsigned OM[152];
    __shared__ float TMP[T_*GS];
    __shared__ float VU[T_];
    __shared__ float SCR[T_];
    __shared__ float PL[HH + 2];
    __shared__ int C1s[T_], CCs[T_], NHs[T_], HOFS[T_ + 1];
    __shared__ int fmeta[FLATCAP];
    __shared__ unsigned char fbt[FLATCAP];

    const int b = blockIdx.x, tid = threadIdx.x;
    const int wid = tid >> 5, lane = tid & 31;

    if (tid < T_) {
        C1s[tid] = g_c1[b*T_ + tid];
        CCs[tid] = g_ccnt[b*T_ + tid];
        NHs[tid] = g_nhit[b*T_ + tid];
    }
    for (int i = tid; i < HH*GS; i += NTB) SWd[i] = Wd[i];
    for (int i = tid; i < G3; i += NTB) BH[i] = bh[i];
    __syncthreads();
    if (tid == 0) {
        int s = 0;
        #pragma unroll
        for (int t = 0; t < T_; t++) { HOFS[t] = s; s += NHs[t]; }
        HOFS[T_] = s;
    }
    __syncthreads();
    const int TH = HOFS[T_];

    // ===== stage 1: all non-chain hits (flat across t, groups of 4) =====
    for (int lo = 0; lo < TH; lo += FLATCAP) {
        const int hi = min(lo + FLATCAP, TH);
        if (wid < T_) {
            for (int i = lane; i < NHs[wid]; i += 32) {
                int gp = HOFS[wid] + i;
                if (gp >= lo && gp < hi) {
                    fmeta[gp - lo] = g_hmeta[(b*T_ + wid)*MAXM + i];
                    fbt[gp - lo] = (unsigned char)wid;
                }
            }
        }
        __syncthreads();
        const int cnt = hi - lo;
        for (int c0 = 0; c0 < cnt; c0 += 4) {
            int nc = min(4, cnt - c0);
            for (int task = tid; task < 4*152; task += NTB) {
                int g = task / 152, k = task - g*152;
                float v = 0.f;
                if (g < nc && k < HH) {
                    int bt = b*T_ + fbt[c0 + g];
                    int meta = fmeta[c0 + g];
                    int srcpos = (meta >> 8) & 0xFF;
                    const float* src = (meta & (1 << 16))
                        ? g_h23 + ((size_t)(bt - 1)*MAXM + srcpos)*HH
                        : g_hm1 + ((size_t)(bt - 1)*MAXM + srcpos)*HH;
                    v = src[k];
                }
                HP[task] = v;
            }
            __syncthreads();
            if (tid < G3) {
                float a0 = 0.f, a1 = 0.f, a2 = 0.f, a3 = 0.f;
                const float4* wrow = (const float4*)(g_WhT + tid*152);
                #pragma unroll
                for (int k4 = 0; k4 < 38; k4++) {
                    float4 w = __ldg(wrow + k4);
                    float4 h0 = *(const float4*)&HP[0*152 + k4*4];
                    float4 h1 = *(const float4*)&HP[1*152 + k4*4];
                    float4 h2 = *(const float4*)&HP[2*152 + k4*4];
                    float4 h3 = *(const float4*)&HP[3*152 + k4*4];
                    a0 += w.x*h0.x + w.y*h0.y + w.z*h0.z + w.w*h0.w;
                    a1 += w.x*h1.x + w.y*h1.y + w.z*h1.z + w.w*h1.w;
                    a2 += w.x*h2.x + w.y*h2.y + w.z*h2.z + w.w*h2.w;
                    a3 += w.x*h3.x + w.y*h3.y + w.z*h3.z + w.w*h3.w;
                }
                GH[0*G3 + tid] = a0; GH[1*G3 + tid] = a1;
                GH[2*G3 + tid] = a2; GH[3*G3 + tid] = a3;
            }
            __syncthreads();
            for (int task = tid; task < nc*HH; task += NTB) {
                int g = task / HH, h = task - g*HH;
                int bt = b*T_ + fbt[c0 + g];
                int r = fmeta[c0 + g] & 0xFF;
                const float* gir = g_gi + ((size_t)bt*MAXM + r)*G3;
                const float* ghg = GH + g*G3;
                float hp = HP[g*152 + h];
                float rr = 1.f / (1.f + __expf(-(__ldg(gir + h)       + BH[h]       + ghg[h])));
                float zz = 1.f / (1.f + __expf(-(__ldg(gir + 150 + h) + BH[150 + h] + ghg[150 + h])));
                float nn = tanhf(__ldg(gir + 300 + h) + rr * (BH[300 + h] + ghg[300 + h]));
                float hv = (1.f - zz) * nn + zz * hp;
                g_hm1[((size_t)bt*MAXM + r)*HH + h] = hv;
                atomicMax(&g_om1u[bt*152 + h], fenc(hv));
            }
            __syncthreads();
        }
        __syncthreads();
    }
    __syncthreads();

    // ===== stage 2: flat OUTs (g_om1u now includes hit rows) =====
    for (int task = tid; task < T_*HH; task += NTB) {
        int t = task / HH, h = task - t*HH;
        int bt = b*T_ + t;
        float o1 = (C1s[t] > 0) ? fdec(g_om1u[bt*152 + h]) : 0.f;
        OUTs[task] = o1 + g_om23[bt*HH + h];
    }
    __syncthreads();

    // ===== stage 3: chain fixups in t-order (rare) =====
    int totcc = 0;
    #pragma unroll
    for (int t = 0; t < T_; t++) totcc += CCs[t];
    if (totcc > 0) {
        for (int t = 0; t < T_; t++) {
            int cc = CCs[t];
            if (cc == 0) continue;
            int bt = b*T_ + t;
            for (int h = tid; h < 152; h += NTB) OM[h] = g_om1u[bt*152 + h];
            __syncthreads();
            for (int ci = 0; ci < cc; ci++) {
                int meta = g_cmeta[bt*MAXM + ci];
                int r = meta & 0xFF, srcpos = (meta >> 8) & 0xFF;
                const float* src = g_hm1 + ((size_t)(bt - 1)*MAXM + srcpos)*HH;
                for (int k = tid; k < 152; k += NTB) HP[k] = (k < HH) ? src[k] : 0.f;
                __syncthreads();
                if (tid < G3) {
                    float a0 = 0.f;
                    const float4* wrow = (const float4*)(g_WhT + tid*152);
                    #pragma unroll
                    for (int k4 = 0; k4 < 38; k4++) {
                        float4 w = __ldg(wrow + k4);
                        float4 h0 = *(const float4*)&HP[k4*4];
                        a0 += w.x*h0.x + w.y*h0.y + w.z*h0.z + w.w*h0.w;
                    }
                    GH[tid] = a0;
                }
                __syncthreads();
                if (tid < HH) {
                    int h = tid;
                    const float* gir = g_gi + ((size_t)bt*MAXM + r)*G3;
                    float hp = HP[h];
                    float rr = 1.f / (1.f + __expf(-(__ldg(gir + h)       + BH[h]       + GH[h])));
                    float zz = 1.f / (1.f + __expf(-(__ldg(gir + 150 + h) + BH[150 + h] + GH[150 + h])));
                    float nn = tanhf(__ldg(gir + 300 + h) + rr * (BH[300 + h] + GH[300 + h]));
                    float hv = (1.f - zz) * nn + zz * hp;
                    g_hm1[((size_t)bt*MAXM + r)*HH + h] = hv;
                    atomicMax(&OM[h], fenc(hv));
                }
                __syncthreads();
            }
            for (int h = tid; h < HH; h += NTB)
                OUTs[t*HH + h] = fdec(OM[h]) + g_om23[bt*HH + h];
            __syncthreads();
        }
    }

    // ===== stage 4: visit attention =====
    for (int task = tid; task < T_*GS; task += NTB) {
        int tt = task >> 5, a = task & 31;
        float acc = __ldg(bd + a);
        const float* o = OUTs + tt*HH;
        #pragma unroll 5
        for (int h = 0; h < HH; h++) acc += o[h] * SWd[h*GS + a];
        TMP[task] = acc;
    }
    __syncthreads();
    if (tid < T_) {
        float acc = 0.f;
        for (int a = 0; a < GS; a++) acc += TMP[tid*GS + a] * __ldg(context + a);
        VU[tid] = acc;
    }
    __syncthreads();
    if (tid < 32) {
        int L = lens[b];
        float v = (tid < T_ && tid < L) ? VU[tid] : -1e30f;
        float mx = v;
        for (int o = 16; o; o >>= 1) mx = fmaxf(mx, __shfl_xor_sync(0xffffffffu, mx, o));
        float e = (tid < T_ && tid < L) ? __expf(v - mx) : 0.f;
        float s = e;
        for (int o = 16; o; o >>= 1) s += __shfl_xor_sync(0xffffffffu, s, o);
        if (tid < T_) SCR[tid] = e / s;
    }
    __syncthreads();
    for (int h = tid; h < HH; h += NTB) {
        float acc = 0.f;
        for (int tt = 0; tt < T_; tt++) acc += SCR[tt] * OUTs[tt*HH + h];
        PL[h] = acc;
    }
    __syncthreads();

    // ===== stage 5: classifier =====
    if (tid < 256) {
        int o4 = tid * 4;
        float4 acc = *(const float4*)(bc + o4);
        const float4* wc4 = (const float4*)Wc + tid;
        #pragma unroll 1
        for (int h0 = 0; h0 < HH; h0 += 10) {
            float4 w[10];
            #pragma unroll
            for (int u = 0; u < 10; u++) w[u] = __ldg(wc4 + (h0 + u)*(ONUM/4));
            #pragma unroll
            for (int u = 0; u < 10; u++) {
                float p = PL[h0 + u];
                acc.x += p * w[u].x; acc.y += p * w[u].y;
                acc.z += p * w[u].z; acc.w += p * w[u].w;
            }
        }
        float4 r;
        r.x = 1.f / (1.f + __expf(-acc.x));
        r.y = 1.f / (1.f + __expf(-acc.y));
        r.z = 1.f / (1.f + __expf(-acc.z));
        r.w = 1.f / (1.f + __expf(-acc.w));
        *(float4*)(out + b*ONUM + o4) = r;
    }
}

extern "C" void kernel_launch(void* const* d_in, const int* in_sizes, int n_in,
                              void* d_out, int out_size)
{
    const float* code_x    = (const float*)d_in[0];
    const float* divided   = (const float*)d_in[1];
    const float* neighbors = (const float*)d_in[2];
    const int*   lens      = (const int*)d_in[3];
    const float* adj       = (const float*)d_in[4];
    const float* c_emb     = (const float*)d_in[5];
    const float* n_emb     = (const float*)d_in[6];
    const float* u_emb     = (const float*)d_in[7];
    const float* Wg = (const float*)d_in[8];  const float* bg = (const float*)d_in[9];
    const float* Wi = (const float*)d_in[10]; const float* bi = (const float*)d_in[11];
    const float* Wh = (const float*)d_in[12]; const float* bh = (const float*)d_in[13];
    const float* Wq = (const float*)d_in[14]; const float* bq = (const float*)d_in[15];
    const float* Wk = (const float*)d_in[16]; const float* bk = (const float*)d_in[17];
    const float* Wv = (const float*)d_in[18]; const float* bv = (const float*)d_in[19];
    const float* Wd = (const float*)d_in[20]; const float* bd = (const float*)d_in[21];
    const float* context = (const float*)d_in[22];
    const float* Wc = (const float*)d_in[23]; const float* bc = (const float*)d_in[24];
    float* out = (float*)d_out;

    cudaFuncSetAttribute(phaseA, cudaFuncAttributeMaxDynamicSharedMemorySize, A_SMEM);

    phaseA<<<B_*T_, NTA, A_SMEM>>>(code_x, divided, neighbors, adj, c_emb, n_emb, u_emb,
                                   Wg, bg, Wi, bi, Wq, bq, Wk, bk, Wv, bv, Wh, bh);
    phaseB<<<B_, NTB>>>(lens, bh, Wd, bd, context, Wc, bc, out);
}

// round 17
// speedup vs baseline: 1.6051x; 1.6051x over previous
#include <cuda_runtime.h>
#include <math.h>
#include <stdint.h>

#define B_ 8
#define T_ 16
#define N_ 1024
#define CS 48
#define GS 32
#define HH 150
#define G3 450
#define ONUM 1024
#define MAXA 160
#define MAXM 80
#define NTA 768
#define NTB 512
#define NTH 512
#define CSRCAP 64

// ------------- device scratch (no cudaMalloc allowed) -------------
__device__ float    g_gi[B_*T_*MAXM*G3];    // GRU input gates at m1 rows
__device__ float    g_h23[B_*T_*MAXM*HH];   // attention hidden at m23 rows
__device__ float    g_om23[B_*T_*HH];       // gated max-pool over m23 rows
__device__ float    g_hm1[B_*T_*MAXM*HH];   // h_m1 rows
__device__ unsigned g_om1u[B_*T_*152];      // ENCODED max over m1 rows
__device__ int      g_c1[B_*T_];
__device__ int      g_nhit[B_*T_];          // non-chain hit count
__device__ int      g_ccnt[B_*T_];          // chain hit count
__device__ int      g_hmeta[B_*T_*MAXM];    // non-chain: r | srcpos<<8 | is23<<16
__device__ int      g_cmeta[B_*T_*MAXM];    // chain:     r | srcpos<<8
__device__ float    g_WhT[G3*152];          // Wh transposed [450][152]
__device__ short    g_csrCol[N_*CSRCAP];    // adj CSR columns
__device__ float    g_csrVal[N_*CSRCAP];    // adj CSR values
__device__ int      g_csrCnt[N_];           // adj CSR row counts

__device__ __forceinline__ unsigned fenc(float f){
    unsigned u = __float_as_uint(f);
    return (u & 0x80000000u) ? ~u : (u | 0x80000000u);
}
__device__ __forceinline__ float fdec(unsigned u){
    return (u & 0x80000000u) ? __uint_as_float(u ^ 0x80000000u) : __uint_as_float(~u);
}

// pack predicate bits for 1024 elements (32 per lane), MLP-32 loads
template<int STRIDE>
__device__ __forceinline__ unsigned pack_bits(const float* __restrict__ p, int lane) {
    float v[32];
    #pragma unroll
    for (int i = 0; i < 32; i++) v[i] = __ldg(p + (size_t)(i*32 + lane)*STRIDE);
    unsigned b = 0;
    #pragma unroll
    for (int i = 0; i < 32; i++) b |= (v[i] > 0.f ? 1u : 0u) << i;
    return b;
}

// ---------------- prep: adj -> CSR, Wh -> WhT ----------------
__global__ void __launch_bounds__(64) prep(const float* __restrict__ adj,
                                           const float* __restrict__ Wh)
{
    const int m = blockIdx.x;
    const int lane = threadIdx.x & 31, wid = threadIdx.x >> 5;
    const unsigned lt = (1u << lane) - 1u;
    if (wid == 0) {
        const float* row = adj + (size_t)m * N_;
        int cnt = 0;
        for (int base = 0; base < N_; base += 32) {
            float v = __ldg(row + base + lane);
            unsigned mk = __ballot_sync(0xffffffffu, v != 0.f);
            if (v != 0.f) {
                int p = cnt + __popc(mk & lt);
                if (p < CSRCAP) { g_csrCol[m*CSRCAP + p] = (short)(base + lane); g_csrVal[m*CSRCAP + p] = v; }
            }
            cnt += __popc(mk);
        }
        if (lane == 0) g_csrCnt[m] = min(cnt, CSRCAP);
    } else {
        for (int i = m*32 + lane; i < G3*152; i += N_*32) {
            int j = i / 152, k = i - j*152;
            g_WhT[i] = (k < HH) ? Wh[k*G3 + j] : 0.f;
        }
    }
}

// ---------------- Phase A smem float offsets ----------------
#define AW_G 0
#define AW_Q 1536
#define AW_K 2560
#define AW_V 3584
#define AB_G 8384
#define AB_Q 8416
#define AB_K 8448
#define AB_V 8480
#define A_OM 8640     // 160 encoded max, om23
#define A_IN 39520    // 160x48
#define A_NP 47200    // 80x48 + pad
// overlays
#define A_CO 8800
#define A_QR 13920
#define A_Qb 24160
#define A_Kb 26720
#define A_Pb 29280
#define A_Vb 39520
#define A_OM1 51520   // 152 encoded max, om1 nonhit
#define A_BH  51672   // 456 (bh)
#define A_TOTF 52128  // -> byte 208512
#define A_SMEM 217056

__global__ void __launch_bounds__(NTA, 1) phaseA(
    const float* __restrict__ code_x, const float* __restrict__ divided,
    const float* __restrict__ neighbors,
    const float* __restrict__ c_emb, const float* __restrict__ n_emb,
    const float* __restrict__ u_emb,
    const float* __restrict__ Wg, const float* __restrict__ bg,
    const float* __restrict__ Wi, const float* __restrict__ bi,
    const float* __restrict__ Wq, const float* __restrict__ bq,
    const float* __restrict__ Wk, const float* __restrict__ bk,
    const float* __restrict__ Wv, const float* __restrict__ bv,
    const float* __restrict__ bh)
{
    extern __shared__ float sm[];
    short* sh      = (short*)((char*)sm + A_TOTF*4);
    short* rowmap  = sh;              // 1024
    short* idxA    = sh + 1024;       // 160 (lists for Nb/Ap/Nbp removed)
    short* m1l     = idxA + 4*MAXA;   // keep original spacing
    short* m23l    = m1l + MAXM;
    short* aiof1   = m23l + MAXM;
    unsigned* amaskC  = (unsigned*)(aiof1 + MAXM);   // 32
    unsigned* nbmaskC = amaskC + 32;
    unsigned* amaskP  = nbmaskC + 32;
    unsigned* nbmaskP = amaskP + 32;
    short* prevmap = (short*)(nbmaskP + 32) + 128;   // 1024 (within old lstP+prevmap span)
    unsigned char* flags   = (unsigned char*)sm + 215648; // 80
    unsigned char* prevhit = (unsigned char*)sm + 215808; // 1024
    int* cnts      = (int*)((char*)sm + 216832);          // 8
    short* nhl     = (short*)((char*)sm + 216864);        // 80

    const int bt = blockIdx.x;
    const int t = bt & 15;
    const int tid = threadIdx.x, lane = tid & 31, wid = tid >> 5;
    const unsigned lt = (1u << lane) - 1u;

    // ===== region 0: init =====
    for (int i = tid; i < (CS*GS)/4; i += NTA)
        ((float4*)(sm + AW_G))[i] = __ldg((const float4*)Wg + i);
    for (int i = tid; i < (GS*GS)/4; i += NTA) {
        ((float4*)(sm + AW_Q))[i] = __ldg((const float4*)Wq + i);
        ((float4*)(sm + AW_K))[i] = __ldg((const float4*)Wk + i);
    }
    for (int i = tid; i < (GS*HH)/4; i += NTA)
        ((float4*)(sm + AW_V))[i] = __ldg((const float4*)Wv + i);
    if (tid < GS) { sm[AB_G + tid] = bg[tid]; sm[AB_Q + tid] = bq[tid]; sm[AB_K + tid] = bk[tid]; }
    for (int i = tid; i < HH; i += NTA) sm[AB_V + i] = bv[i];
    for (int i = tid; i < G3; i += NTA) sm[A_BH + i] = bh[i];
    {
        unsigned negenc = fenc(-1e30f);
        for (int i = tid; i < 160; i += NTA) ((unsigned*)(sm + A_OM))[i] = negenc;
        for (int i = tid; i < 152; i += NTA) ((unsigned*)(sm + A_OM1))[i] = negenc;
    }
    for (int i = tid; i < N_; i += NTA) { prevmap[i] = -1; prevhit[i] = 0; }
    __syncthreads();

    // ===== region 1: masks + lists, one warp per producer =====
    const int base0 = bt * N_;
    if (wid == 0) {            // active cur: mask + idxA + rowmap
        unsigned bits = pack_bits<1>(code_x + base0, lane);
        amaskC[lane] = bits;
        int cnt = 0;
        #pragma unroll
        for (int i = 0; i < 32; i++) {
            unsigned mk = __ballot_sync(0xffffffffu, (bits >> i) & 1u);
            if ((bits >> i) & 1u) {
                int p = cnt + __popc(mk & lt);
                if (p < MAXA) { idxA[p] = (short)(i*32 + lane); rowmap[i*32 + lane] = (short)p; }
            }
            cnt += __popc(mk);
        }
        if (lane == 0) cnts[0] = min(cnt, MAXA);
    } else if (wid == 1) {     // neighbors cur: mask only
        nbmaskC[lane] = pack_bits<1>(neighbors + base0, lane);
    } else if (wid == 2) {     // m1
        unsigned bits = pack_bits<3>(divided + (size_t)base0*3 + 0, lane);
        int cnt = 0;
        #pragma unroll
        for (int i = 0; i < 32; i++) {
            unsigned mk = __ballot_sync(0xffffffffu, (bits >> i) & 1u);
            if ((bits >> i) & 1u) {
                int p = cnt + __popc(mk & lt);
                if (p < MAXM) m1l[p] = (short)(i*32 + lane);
            }
            cnt += __popc(mk);
        }
        if (lane == 0) cnts[4] = min(cnt, MAXM);
    } else if (wid == 3) {     // m23 + flags
        unsigned b2 = pack_bits<3>(divided + (size_t)base0*3 + 1, lane);
        unsigned b3 = pack_bits<3>(divided + (size_t)base0*3 + 2, lane);
        unsigned be = b2 | b3;
        int cnt = 0;
        #pragma unroll
        for (int i = 0; i < 32; i++) {
            unsigned mk = __ballot_sync(0xffffffffu, (be >> i) & 1u);
            if ((be >> i) & 1u) {
                int p = cnt + __popc(mk & lt);
                if (p < MAXM) { m23l[p] = (short)(i*32 + lane); flags[p] = (b2 >> i) & 1u; }
            }
            cnt += __popc(mk);
        }
        if (lane == 0) cnts[5] = min(cnt, MAXM);
    } else if (wid == 4) {     // active prev: mask only
        amaskP[lane] = (t > 0) ? pack_bits<1>(code_x + base0 - N_, lane) : 0u;
    } else if (wid == 5) {     // neighbors prev: mask only
        nbmaskP[lane] = (t > 0) ? pack_bits<1>(neighbors + base0 - N_, lane) : 0u;
    } else if (wid == 6 && t > 0) {  // prevmap: prev m1 positions
        unsigned bits = pack_bits<3>(divided + (size_t)(base0 - N_)*3 + 0, lane);
        int cnt = 0;
        #pragma unroll
        for (int i = 0; i < 32; i++) {
            unsigned mk = __ballot_sync(0xffffffffu, (bits >> i) & 1u);
            if ((bits >> i) & 1u) {
                int p = cnt + __popc(mk & lt);
                if (p < MAXM) prevmap[i*32 + lane] = (short)p;
            }
            cnt += __popc(mk);
        }
    } else if (wid == 7 && t > 0) {  // prevmap: prev m23 positions (valid t>=2)
        unsigned b2 = pack_bits<3>(divided + (size_t)(base0 - N_)*3 + 1, lane);
        unsigned b3 = pack_bits<3>(divided + (size_t)(base0 - N_)*3 + 2, lane);
        unsigned be = b2 | b3;
        int cnt = 0;
        #pragma unroll
        for (int i = 0; i < 32; i++) {
            unsigned mk = __ballot_sync(0xffffffffu, (be >> i) & 1u);
            if ((be >> i) & 1u) {
                int p = cnt + __popc(mk & lt);
                if (p < MAXM && t >= 2) prevmap[i*32 + lane] = (short)(p | 0x4000);
            }
            cnt += __popc(mk);
        }
    } else if (wid == 8 && t >= 2) { // prevhit
        const float* dp = divided + (size_t)(base0 - 2*N_)*3;
        for (int i0 = 0; i0 < 32; i0 += 8) {
            float a[8], b2[8], c[8];
            #pragma unroll
            for (int u = 0; u < 8; u++) {
                int n = (i0 + u)*32 + lane;
                a[u]  = __ldg(dp + n*3 + 0);
                b2[u] = __ldg(dp + n*3 + 1);
                c[u]  = __ldg(dp + n*3 + 2);
            }
            #pragma unroll
            for (int u = 0; u < 8; u++) {
                int n = (i0 + u)*32 + lane;
                prevhit[n] = (a[u] > 0.f) || (((b2[u] > 0.f) || (c[u] > 0.f)) && t >= 3);
            }
        }
    }
    __syncthreads();

    const int cA = cnts[0];
    const int c1 = cnts[4], c23 = cnts[5];

    // ===== region 2: hit classification =====
    if (wid == 0) {
        int nnc = 0, ncc = 0, nnh = 0;
        for (int base = 0; base < c1; base += 32) {
            int r = base + lane;
            int n = (r < c1) ? m1l[r] : 0;
            short pm = (r < c1) ? prevmap[n] : (short)-1;
            bool inb = r < c1;
            bool hit = inb && pm >= 0;
            bool is23 = hit && (pm & 0x4000);
            bool chain = hit && !is23 && prevhit[n];
            bool nonch = hit && !chain;
            bool nonhit = inb && !hit;
            unsigned mk1 = __ballot_sync(0xffffffffu, nonch);
            unsigned mk2 = __ballot_sync(0xffffffffu, chain);
            unsigned mk3 = __ballot_sync(0xffffffffu, nonhit);
            if (inb) {
                int srcpos = pm & 0x3FFF;
                if (nonch) {
                    int p = nnc + __popc(mk1 & lt);
                    g_hmeta[bt*MAXM + p] = r | (srcpos << 8) | ((is23 ? 1 : 0) << 16);
                }
                if (chain) {
                    int p = ncc + __popc(mk2 & lt);
                    g_cmeta[bt*MAXM + p] = r | (srcpos << 8);
                }
                if (nonhit) {
                    int p = nnh + __popc(mk3 & lt);
                    nhl[p] = (short)r;
                }
            }
            nnc += __popc(mk1); ncc += __popc(mk2); nnh += __popc(mk3);
        }
        if (lane == 0) { g_nhit[bt] = nnc; g_ccnt[bt] = ncc; g_c1[bt] = c1; cnts[6] = nnh; }
    }
    if (t > 0)
        for (int i = tid; i < c23; i += NTA)
            if ((flags[i] & 1) && neighbors[(bt - 1)*N_ + m23l[i]] > 0.f) flags[i] |= 2;
    {
        int c1p = (c1 + 7) & ~7;
        for (int i = tid; i < c1p; i += NTA) aiof1[i] = (i < c1) ? rowmap[m1l[i]] : (short)0;
    }
    __syncthreads();

    // ---- S1: CSR aggregation at active rows ----
    for (int task = tid; task < cA*4; task += NTA) {
        int ai = task >> 2, ch = (task & 3) * 12;
        int m = idxA[ai];
        int cnt = __ldg(&g_csrCnt[m]);
        const short* ccol = g_csrCol + m*CSRCAP;
        const float* cval = g_csrVal + m*CSRCAP;
        float acc[12];
        {
            const float4* em = (const float4*)(c_emb + m*CS + ch);
            float4 e0 = __ldg(em), e1 = __ldg(em + 1), e2 = __ldg(em + 2);
            acc[0]=e0.x; acc[1]=e0.y; acc[2]=e0.z; acc[3]=e0.w;
            acc[4]=e1.x; acc[5]=e1.y; acc[6]=e1.z; acc[7]=e1.w;
            acc[8]=e2.x; acc[9]=e2.y; acc[10]=e2.z; acc[11]=e2.w;
        }
        for (int k0 = 0; k0 < cnt; k0 += 8) {
            int nn[8]; float av[8];
            #pragma unroll
            for (int u = 0; u < 8; u++) {
                int k = k0 + u;
                nn[u] = (k < cnt) ? (int)__ldg(ccol + k) : -1;
                av[u] = (k < cnt) ? __ldg(cval + k) : 0.f;
            }
            #pragma unroll
            for (int u = 0; u < 8; u++) {
                int n = nn[u];
                if (n < 0) continue;
                bool act = (amaskC[n & 31] >> (n >> 5)) & 1u;
                bool nb  = (nbmaskC[n & 31] >> (n >> 5)) & 1u;
                if (act) {
                    float a = av[u];
                    const float4* p = (const float4*)(c_emb + n*CS + ch);
                    float4 x0 = __ldg(p), x1 = __ldg(p + 1), x2 = __ldg(p + 2);
                    acc[0]+=a*x0.x; acc[1]+=a*x0.y; acc[2]+=a*x0.z; acc[3]+=a*x0.w;
                    acc[4]+=a*x1.x; acc[5]+=a*x1.y; acc[6]+=a*x1.z; acc[7]+=a*x1.w;
                    acc[8]+=a*x2.x; acc[9]+=a*x2.y; acc[10]+=a*x2.z; acc[11]+=a*x2.w;
                }
                if (nb) {
                    float a = av[u];
                    const float4* p = (const float4*)(n_emb + n*CS + ch);
                    float4 x0 = __ldg(p), x1 = __ldg(p + 1), x2 = __ldg(p + 2);
                    acc[0]+=a*x0.x; acc[1]+=a*x0.y; acc[2]+=a*x0.z; acc[3]+=a*x0.w;
                    acc[4]+=a*x1.x; acc[5]+=a*x1.y; acc[6]+=a*x1.z; acc[7]+=a*x1.w;
                    acc[8]+=a*x2.x; acc[9]+=a*x2.y; acc[10]+=a*x2.z; acc[11]+=a*x2.w;
                }
            }
        }
        float* o = sm + A_IN + ai*CS + ch;
        #pragma unroll
        for (int c = 0; c < 12; c++) o[c] = acc[c];
    }
    // ---- S1b: CSR no_{t-1} input at m2 rows ----
    if (t > 0)
        for (int task = tid; task < c23*4; task += NTA) {
            int mi = task >> 2, ch = (task & 3) * 12;
            float acc[12];
            #pragma unroll
            for (int c = 0; c < 12; c++) acc[c] = 0.f;
            if (flags[mi] & 2) {
                int m = m23l[mi];
                int cnt = __ldg(&g_csrCnt[m]);
                const short* ccol = g_csrCol + m*CSRCAP;
                const float* cval = g_csrVal + m*CSRCAP;
                {
                    const float4* em = (const float4*)(n_emb + m*CS + ch);
                    float4 e0 = __ldg(em), e1 = __ldg(em + 1), e2 = __ldg(em + 2);
                    acc[0]=e0.x; acc[1]=e0.y; acc[2]=e0.z; acc[3]=e0.w;
                    acc[4]=e1.x; acc[5]=e1.y; acc[6]=e1.z; acc[7]=e1.w;
                    acc[8]=e2.x; acc[9]=e2.y; acc[10]=e2.z; acc[11]=e2.w;
                }
                for (int k0 = 0; k0 < cnt; k0 += 8) {
                    int nn[8]; float av[8];
                    #pragma unroll
                    for (int u = 0; u < 8; u++) {
                        int k = k0 + u;
                        nn[u] = (k < cnt) ? (int)__ldg(ccol + k) : -1;
                        av[u] = (k < cnt) ? __ldg(cval + k) : 0.f;
                    }
                    #pragma unroll
                    for (int u = 0; u < 8; u++) {
                        int n = nn[u];
                        if (n < 0) continue;
                        bool act = (amaskP[n & 31] >> (n >> 5)) & 1u;
                        bool nb  = (nbmaskP[n & 31] >> (n >> 5)) & 1u;
                        if (act) {
                            float a = av[u];
                            const float4* p = (const float4*)(c_emb + n*CS + ch);
                            float4 x0 = __ldg(p), x1 = __ldg(p + 1), x2 = __ldg(p + 2);
                            acc[0]+=a*x0.x; acc[1]+=a*x0.y; acc[2]+=a*x0.z; acc[3]+=a*x0.w;
                            acc[4]+=a*x1.x; acc[5]+=a*x1.y; acc[6]+=a*x1.z; acc[7]+=a*x1.w;
                            acc[8]+=a*x2.x; acc[9]+=a*x2.y; acc[10]+=a*x2.z; acc[11]+=a*x2.w;
                        }
                        if (nb) {
                            float a = av[u];
                            const float4* p = (const float4*)(n_emb + n*CS + ch);
                            float4 x0 = __ldg(p), x1 = __ldg(p + 1), x2 = __ldg(p + 2);
                            acc[0]+=a*x0.x; acc[1]+=a*x0.y; acc[2]+=a*x0.z; acc[3]+=a*x0.w;
                            acc[4]+=a*x1.x; acc[5]+=a*x1.y; acc[6]+=a*x1.z; acc[7]+=a*x1.w;
                            acc[8]+=a*x2.x; acc[9]+=a*x2.y; acc[10]+=a*x2.z; acc[11]+=a*x2.w;
                        }
                    }
                }
            }
            float* o = sm + A_NP + mi*CS + ch;
            #pragma unroll
            for (int c = 0; c < 12; c++) o[c] = acc[c];
        }
    __syncthreads();

    // ---- S2: co = lrelu(in48 @ Wg + bg); qrows ----
    for (int task = tid; task < cA*GS; task += NTA) {
        int ai = task >> 5, g = task & 31;
        float acc = sm[AB_G + g];
        const float* in = sm + A_IN + ai*CS;
        #pragma unroll 8
        for (int c = 0; c < CS; c++) acc += in[c] * sm[AW_G + c*GS + g];
        sm[A_CO + task] = acc > 0.f ? acc : 0.01f * acc;
    }
    if (t > 0)
        for (int task = tid; task < c23*GS; task += NTA) {
            int mi = task >> 5, g = task & 31;
            float v;
            if (flags[mi] & 1) {
                float acc = sm[AB_G + g];
                const float* in = sm + A_NP + mi*CS;
                #pragma unroll 8
                for (int c = 0; c < CS; c++) acc += in[c] * sm[AW_G + c*GS + g];
                v = acc > 0.f ? acc : 0.01f * acc;
            } else {
                v = u_emb[m23l[mi]*GS + g];
            }
            sm[A_QR + task] = v;
        }
    __syncthreads();

    // ---- S3: gi at m1 rows (Wi prefetch-16); q/k/v (t>0) ----
    if (c1 > 0) {
        int ng = (c1 + 7) >> 3;
        for (int task = tid; task < G3*ng; task += NTA) {
            int j = task % G3, grp = task / G3, r0 = grp * 8;
            float acc[8];
            int ai[8];
            #pragma unroll
            for (int g = 0; g < 8; g++) { acc[g] = 0.f; ai[g] = aiof1[r0 + g]; }
            #pragma unroll 1
            for (int c0 = 0; c0 < GS; c0 += 16) {
                float w[16];
                #pragma unroll
                for (int u = 0; u < 16; u++) w[u] = __ldg(Wi + (c0 + u)*G3 + j);
                #pragma unroll
                for (int u = 0; u < 16; u++) {
                    #pragma unroll
                    for (int g = 0; g < 8; g++)
                        acc[g] += sm[A_CO + ai[g]*GS + c0 + u] * w[u];
                }
            }
            float bij = __ldg(bi + j);
            int nr = min(8, c1 - r0);
            #pragma unroll
            for (int g = 0; g < 8; g++)
                if (g < nr) g_gi[((size_t)bt*MAXM + r0 + g)*G3 + j] = acc[g] + bij;
        }
    }
    if (t > 0 && c23 > 0) {
        for (int task = tid; task < c23*GS; task += NTA) {
            int i = task >> 5, a = task & 31;
            const float* qr = sm + A_QR + i*GS;
            int ai = rowmap[m23l[i]];
            const float* co = sm + A_CO + ai*GS;
            float accq = sm[AB_Q + a], acck = sm[AB_K + a];
            #pragma unroll
            for (int g = 0; g < GS; g++) {
                accq += qr[g] * sm[AW_Q + g*GS + a];
                acck += co[g] * sm[AW_K + g*GS + a];
            }
            sm[A_Qb + task] = accq;
            sm[A_Kb + task] = acck;
        }
        for (int task = tid; task < c23*HH; task += NTA) {
            int i = task / HH, h = task - i*HH;
            const float* qr = sm + A_QR + i*GS;
            float acc = sm[AB_V + h];
            #pragma unroll
            for (int g = 0; g < GS; g++) acc += qr[g] * sm[AW_V + g*HH + h];
            sm[A_Vb + i*HH + h] = acc;
        }
    }
    __syncthreads();

    // ---- S4: scores + softmax (warp per query) ----
    if (t > 0 && c23 > 0) {
        const float scale = 0.17677669529663687f;
        for (int i = wid; i < c23; i += NTA/32) {
            const float* qi = sm + A_Qb + i*GS;
            float mx = -1e30f;
            for (int j = lane; j < c23; j += 32) {
                const float* kj = sm + A_Kb + j*GS;
                float s = 0.f;
                #pragma unroll
                for (int g = 0; g < GS; g++) s += qi[g] * kj[g];
                s *= scale;
                sm[A_Pb + i*MAXM + j] = s;
                mx = fmaxf(mx, s);
            }
            for (int o = 16; o; o >>= 1) mx = fmaxf(mx, __shfl_xor_sync(0xffffffffu, mx, o));
            float sum = 0.f;
            for (int j = lane; j < c23; j += 32) {
                float e = __expf(sm[A_Pb + i*MAXM + j] - mx);
                sm[A_Pb + i*MAXM + j] = e; sum += e;
            }
            for (int o = 16; o; o >>= 1) sum += __shfl_xor_sync(0xffffffffu, sum, o);
            float inv = 1.f / sum;
            for (int j = lane; j < c23; j += 32) sm[A_Pb + i*MAXM + j] *= inv;
        }
    }
    __syncthreads();

    // ---- S5: h_m23 + om23 (4 independent accumulator chains) ----
    if (t > 0 && c23 > 0) {
        unsigned* OM = (unsigned*)(sm + A_OM);
        for (int task = tid; task < c23*HH; task += NTA) {
            int i = task / HH, h = task - i*HH;
            const float* pr = sm + A_Pb + i*MAXM;
            const float* vb = sm + A_Vb + h;
            float a0 = 0.f, a1 = 0.f, a2 = 0.f, a3 = 0.f;
            int j = 0;
            for (; j + 3 < c23; j += 4) {
                a0 += pr[j]     * vb[j*HH];
                a1 += pr[j + 1] * vb[(j + 1)*HH];
                a2 += pr[j + 2] * vb[(j + 2)*HH];
                a3 += pr[j + 3] * vb[(j + 3)*HH];
            }
            float acc = (a0 + a1) + (a2 + a3);
            for (; j < c23; j++) acc += pr[j] * vb[j*HH];
            float hv = tanhf(acc);
            g_h23[((size_t)bt*MAXM + i)*HH + h] = hv;
            atomicMax(OM + h, fenc(hv));
        }
    }
    // ---- S6: non-hit GRU rows via compact list ----
    {
        const int nnh = cnts[6];
        unsigned* OM1 = (unsigned*)(sm + A_OM1);
        const int ntask = nnh*HH;
        for (int task = tid; task < ntask; task += NTA) {
            int r = nhl[task / HH], h = task % HH;
            const float* g1 = g_gi + ((size_t)bt*MAXM + r)*G3;
            float gr = __ldg(g1 + h), gz = __ldg(g1 + 150 + h), gn = __ldg(g1 + 300 + h);
            float rr = 1.f / (1.f + __expf(-(gr + sm[A_BH + h])));
            float zz = 1.f / (1.f + __expf(-(gz + sm[A_BH + 150 + h])));
            float nn = tanhf(gn + rr * sm[A_BH + 300 + h]);
            float hv = (1.f - zz) * nn;
            g_hm1[((size_t)bt*MAXM + r)*HH + h] = hv;
            atomicMax(OM1 + h, fenc(hv));
        }
    }
    __syncthreads();
    for (int h = tid; h < HH; h += NTA) {
        g_om1u[bt*152 + h] = ((unsigned*)(sm + A_OM1))[h];
        g_om23[bt*HH + h] = (t > 0 && c23 > 0) ? fdec(((unsigned*)(sm + A_OM))[h]) : 0.f;
    }
}

// ---------------- Phase H: non-chain hits, parallel over (b,t) ----------------
__global__ void __launch_bounds__(NTH) phaseH(const float* __restrict__ bh)
{
    __shared__ float HP[4*152];
    __shared__ float GH[4*G3];
    __shared__ float BH[G3];

    const int bt = blockIdx.x, tid = threadIdx.x;
    const int nh = g_nhit[bt];
    if (nh == 0) return;
    for (int i = tid; i < G3; i += NTH) BH[i] = bh[i];
    __syncthreads();

    for (int c0 = 0; c0 < nh; c0 += 4) {
        int nc = min(4, nh - c0);
        for (int task = tid; task < 4*152; task += NTH) {
            int g = task / 152, k = task - g*152;
            float v = 0.f;
            if (g < nc && k < HH) {
                int meta = g_hmeta[bt*MAXM + c0 + g];
                int srcpos = (meta >> 8) & 0xFF;
                const float* src = (meta & (1 << 16))
                    ? g_h23 + ((size_t)(bt - 1)*MAXM + srcpos)*HH
                    : g_hm1 + ((size_t)(bt - 1)*MAXM + srcpos)*HH;
                v = src[k];
            }
            HP[task] = v;
        }
        __syncthreads();
        if (tid < G3) {
            float a0 = 0.f, a1 = 0.f, a2 = 0.f, a3 = 0.f;
            const float4* wrow = (const float4*)(g_WhT + tid*152);
            #pragma unroll
            for (int k4 = 0; k4 < 38; k4++) {
                float4 w = __ldg(wrow + k4);
                float4 h0 = *(const float4*)&HP[0*152 + k4*4];
                float4 h1 = *(const float4*)&HP[1*152 + k4*4];
                float4 h2 = *(const float4*)&HP[2*152 + k4*4];
                float4 h3 = *(const float4*)&HP[3*152 + k4*4];
                a0 += w.x*h0.x + w.y*h0.y + w.z*h0.z + w.w*h0.w;
                a1 += w.x*h1.x + w.y*h1.y + w.z*h1.z + w.w*h1.w;
                a2 += w.x*h2.x + w.y*h2.y + w.z*h2.z + w.w*h2.w;
                a3 += w.x*h3.x + w.y*h3.y + w.z*h3.z + w.w*h3.w;
            }
            GH[0*G3 + tid] = a0; GH[1*G3 + tid] = a1;
            GH[2*G3 + tid] = a2; GH[3*G3 + tid] = a3;
        }
        __syncthreads();
        for (int task = tid; task < nc*HH; task += NTH) {
            int g = task / HH, h = task - g*HH;
            int meta = g_hmeta[bt*MAXM + c0 + g];
            int r = meta & 0xFF;
            const float* gir = g_gi + ((size_t)bt*MAXM + r)*G3;
            const float* ghg = GH + g*G3;
            float hp = HP[g*152 + h];
            float rr = 1.f / (1.f + __expf(-(__ldg(gir + h)       + BH[h]       + ghg[h])));
            float zz = 1.f / (1.f + __expf(-(__ldg(gir + 150 + h) + BH[150 + h] + ghg[150 + h])));
            float nn = tanhf(__ldg(gir + 300 + h) + rr * (BH[300 + h] + ghg[300 + h]));
            float hv = (1.f - zz) * nn + zz * hp;
            g_hm1[((size_t)bt*MAXM + r)*HH + h] = hv;
            atomicMax(&g_om1u[bt*152 + h], fenc(hv));
        }
        __syncthreads();
    }
}

// ---------------- Phase B: chain fixups (rare) + attention + classifier ----------------
__global__ void __launch_bounds__(NTB, 1) phaseB(
    const int* __restrict__ lens,
    const float* __restrict__ bh,
    const float* __restrict__ Wd, const float* __restrict__ bd,
    const float* __restrict__ context,
    const float* __restrict__ Wc, const float* __restrict__ bc,
    float* __restrict__ out)
{
    __shared__ float OUTs[T_*HH];
    __shared__ float SWd[HH*GS];
    __shared__ float HP[152];
    __shared__ float GH[G3];
    __shared__ float BH[G3];
    __shared__ unsigned OM[152];
    __shared__ float TMP[T_*GS];
    __shared__ float VU[T_];
    __shared__ float SCR[T_];
    __shared__ float PL[HH + 2];
    __shared__ int C1s[T_], CCs[T_];

    const int b = blockIdx.x, tid = threadIdx.x;

    if (tid < T_) { C1s[tid] = g_c1[b*T_ + tid]; CCs[tid] = g_ccnt[b*T_ + tid]; }
    for (int i = tid; i < HH*GS; i += NTB) SWd[i] = Wd[i];
    for (int i = tid; i < G3; i += NTB) BH[i] = bh[i];
    __syncthreads();

    // flat upfront OUTs (common path)
    for (int task = tid; task < T_*HH; task += NTB) {
        int t = task / HH, h = task - t*HH;
        int bt = b*T_ + t;
        float o1 = (C1s[t] > 0) ? fdec(g_om1u[bt*152 + h]) : 0.f;
        OUTs[task] = o1 + g_om23[bt*HH + h];
    }
    __syncthreads();

    int totcc = 0;
    #pragma unroll
    for (int t = 0; t < T_; t++) totcc += CCs[t];

    if (totcc > 0) {
        for (int t = 0; t < T_; t++) {
            int cc = CCs[t];
            if (cc == 0) continue;
            int bt = b*T_ + t;
            for (int h = tid; h < 152; h += NTB) OM[h] = g_om1u[bt*152 + h];
            __syncthreads();
            for (int ci = 0; ci < cc; ci++) {
                int meta = g_cmeta[bt*MAXM + ci];
                int r = meta & 0xFF, srcpos = (meta >> 8) & 0xFF;
                const float* src = g_hm1 + ((size_t)(bt - 1)*MAXM + srcpos)*HH;
                for (int k = tid; k < 152; k += NTB) HP[k] = (k < HH) ? src[k] : 0.f;
                __syncthreads();
                if (tid < G3) {
                    float a0 = 0.f;
                    const float4* wrow = (const float4*)(g_WhT + tid*152);
                    #pragma unroll
                    for (int k4 = 0; k4 < 38; k4++) {
                        float4 w = __ldg(wrow + k4);
                        float4 h0 = *(const float4*)&HP[k4*4];
                        a0 += w.x*h0.x + w.y*h0.y + w.z*h0.z + w.w*h0.w;
                    }
                    GH[tid] = a0;
                }
                __syncthreads();
                if (tid < HH) {
                    int h = tid;
                    const float* gir = g_gi + ((size_t)bt*MAXM + r)*G3;
                    float hp = HP[h];
                    float rr = 1.f / (1.f + __expf(-(__ldg(gir + h)       + BH[h]       + GH[h])));
                    float zz = 1.f / (1.f + __expf(-(__ldg(gir + 150 + h) + BH[150 + h] + GH[150 + h])));
                    float nn = tanhf(__ldg(gir + 300 + h) + rr * (BH[300 + h] + GH[300 + h]));
                    float hv = (1.f - zz) * nn + zz * hp;
                    g_hm1[((size_t)bt*MAXM + r)*HH + h] = hv;
                    atomicMax(&OM[h], fenc(hv));
                }
                __syncthreads();
            }
            for (int h = tid; h < HH; h += NTB)
                OUTs[t*HH + h] = fdec(OM[h]) + g_om23[bt*HH + h];
            __syncthreads();
        }
    }

    // ---- visit attention (Wd in smem) ----
    for (int task = tid; task < T_*GS; task += NTB) {
        int tt = task >> 5, a = task & 31;
        float acc = __ldg(bd + a);
        const float* o = OUTs + tt*HH;
        #pragma unroll 5
        for (int h = 0; h < HH; h++) acc += o[h] * SWd[h*GS + a];
        TMP[task] = acc;
    }
    __syncthreads();
    if (tid < T_) {
        float acc = 0.f;
        for (int a = 0; a < GS; a++) acc += TMP[tid*GS + a] * __ldg(context + a);
        VU[tid] = acc;
    }
    __syncthreads();
    if (tid < 32) {
        int L = lens[b];
        float v = (tid < T_ && tid < L) ? VU[tid] : -1e30f;
        float mx = v;
        for (int o = 16; o; o >>= 1) mx = fmaxf(mx, __shfl_xor_sync(0xffffffffu, mx, o));
        float e = (tid < T_ && tid < L) ? __expf(v - mx) : 0.f;
        float s = e;
        for (int o = 16; o; o >>= 1) s += __shfl_xor_sync(0xffffffffu, s, o);
        if (tid < T_) SCR[tid] = e / s;
    }
    __syncthreads();
    for (int h = tid; h < HH; h += NTB) {
        float acc = 0.f;
        for (int tt = 0; tt < T_; tt++) acc += SCR[tt] * OUTs[tt*HH + h];
        PL[h] = acc;
    }
    __syncthreads();

    // ---- classifier: 256 threads x 4 outputs, prefetch-10 float4 ----
    if (tid < 256) {
        int o4 = tid * 4;
        float4 acc = *(const float4*)(bc + o4);
        const float4* wc4 = (const float4*)Wc + tid;
        #pragma unroll 1
        for (int h0 = 0; h0 < HH; h0 += 10) {
            float4 w[10];
            #pragma unroll
            for (int u = 0; u < 10; u++) w[u] = __ldg(wc4 + (h0 + u)*(ONUM/4));
            #pragma unroll
            for (int u = 0; u < 10; u++) {
                float p = PL[h0 + u];
                acc.x += p * w[u].x; acc.y += p * w[u].y;
                acc.z += p * w[u].z; acc.w += p * w[u].w;
            }
        }
        float4 r;
        r.x = 1.f / (1.f + __expf(-acc.x));
        r.y = 1.f / (1.f + __expf(-acc.y));
        r.z = 1.f / (1.f + __expf(-acc.z));
        r.w = 1.f / (1.f + __expf(-acc.w));
        *(float4*)(out + b*ONUM + o4) = r;
    }
}

extern "C" void kernel_launch(void* const* d_in, const int* in_sizes, int n_in,
                              void* d_out, int out_size)
{
    const float* code_x    = (const float*)d_in[0];
    const float* divided   = (const float*)d_in[1];
    const float* neighbors = (const float*)d_in[2];
    const int*   lens      = (const int*)d_in[3];
    const float* adj       = (const float*)d_in[4];
    const float* c_emb     = (const float*)d_in[5];
    const float* n_emb     = (const float*)d_in[6];
    const float* u_emb     = (const float*)d_in[7];
    const float* Wg = (const float*)d_in[8];  const float* bg = (const float*)d_in[9];
    const float* Wi = (const float*)d_in[10]; const float* bi = (const float*)d_in[11];
    const float* Wh = (const float*)d_in[12]; const float* bh = (const float*)d_in[13];
    const float* Wq = (const float*)d_in[14]; const float* bq = (const float*)d_in[15];
    const float* Wk = (const float*)d_in[16]; const float* bk = (const float*)d_in[17];
    const float* Wv = (const float*)d_in[18]; const float* bv = (const float*)d_in[19];
    const float* Wd = (const float*)d_in[20]; const float* bd = (const float*)d_in[21];
    const float* context = (const float*)d_in[22];
    const float* Wc = (const float*)d_in[23]; const float* bc = (const float*)d_in[24];
    float* out = (float*)d_out;

    cudaFuncSetAttribute(phaseA, cudaFuncAttributeMaxDynamicSharedMemorySize, A_SMEM);

    prep<<<N_, 64>>>(adj, Wh);
    phaseA<<<B_*T_, NTA, A_SMEM>>>(code_x, divided, neighbors, c_emb, n_emb, u_emb,
                                   Wg, bg, Wi, bi, Wq, bq, Wk, bk, Wv, bv, bh);
    phaseH<<<B_*T_, NTH>>>(bh);
    phaseB<<<B_, NTB>>>(lens, bh, Wd, bd, context, Wc, bc, out);
}